// round 4
// baseline (speedup 1.0000x reference)
#include <cuda_runtime.h>

#define Hh 100
#define Ww 136
#define HW (Hh * Ww)        // 13600
#define OH (2 * Hh)         // 200
#define OW (2 * Ww)         // 272
#define OHW (OH * OW)       // 54400
#define NP 169
#define MAXI 512

typedef unsigned long long ull;

__device__ float g_logits[MAXI * HW];
__device__ float g_inter[MAXI];
__device__ float g_ux[MAXI];
__device__ float g_ut[MAXI];

// ---- packed f32x2 helpers (sm_100+) ----
__device__ __forceinline__ ull pk2(float lo, float hi) {
    ull r; asm("mov.b64 %0, {%1,%2};" : "=l"(r) : "f"(lo), "f"(hi)); return r;
}
__device__ __forceinline__ ull fma2(ull a, ull b, ull c) {
    ull d; asm("fma.rn.f32x2 %0, %1, %2, %3;" : "=l"(d) : "l"(a), "l"(b), "l"(c)); return d;
}
__device__ __forceinline__ ull relu2(ull a) {
    float x, y;
    asm("mov.b64 {%0,%1}, %2;" : "=f"(x), "=f"(y) : "l"(a));
    x = fmaxf(x, 0.0f); y = fmaxf(y, 0.0f);
    ull r; asm("mov.b64 %0, {%1,%2};" : "=l"(r) : "f"(x), "f"(y)); return r;
}
__device__ __forceinline__ void upk2(ull a, float& x, float& y) {
    asm("mov.b64 {%0,%1}, %2;" : "=f"(x), "=f"(y) : "l"(a));
}

// ---------------------------------------------------------------------------
// Kernel A: dynamic mask head -> logits.
// 2 blocks per instance (tail-wave reduction); 8 pixels/thread as 4 f32x2
// pairs so each SMEM weight fetch feeds 4 independent FMA chains.
// ---------------------------------------------------------------------------
__global__ __launch_bounds__(256) void logits_kernel(
    const float* __restrict__ feats,
    const float* __restrict__ params,
    const float* __restrict__ locs,
    const int*   __restrict__ im_inds,
    const int*   __restrict__ fpn)
{
    const int inst = blockIdx.x >> 1;
    const int half = blockIdx.x & 1;
    const int tid  = threadIdx.x;

    __shared__ __align__(16) ull sw0[8][12];   // [j][0..9]=w, [10]=bias
    __shared__ __align__(16) ull sw1[8][10];   // [j][0..7]=w, [8]=bias
    __shared__ __align__(16) ull sw2[10];      // [0..7]=w, [8]=bias

    for (int i = tid; i < NP; i += 256) {
        float w = params[inst * NP + i];
        ull d = pk2(w, w);
        if      (i < 80)  sw0[i / 10][i % 10] = d;
        else if (i < 144) { int k = i - 80; sw1[k >> 3][k & 7] = d; }
        else if (i < 152) sw2[i - 144] = d;
        else if (i < 160) sw0[i - 152][10] = d;
        else if (i < 168) sw1[i - 160][8] = d;
        else              sw2[8] = d;
    }
    __syncthreads();

    const float cx = locs[inst * 2 + 0];
    const float cy = locs[inst * 2 + 1];
    const float inv_soi = 1.0f / (float)(8 << fpn[inst]);
    const float step = -8.0f * inv_soi;
    const float* __restrict__ fb = feats + (size_t)im_inds[inst] * 8 * HW;
    float* __restrict__ Lg = g_logits + (size_t)inst * HW;

    // 8-px units: HW/8 = 1700 (Ww=17*8, units never cross rows). Half = 850.
    const int NU   = HW / 8;          // 1700
    const int ubeg = half * (NU / 2); // 0 or 850
    const int uend = ubeg + (NU / 2);

    for (int u = ubeg + tid; u < uend; u += 256) {
        const int p  = u * 8;
        const int py = p / Ww;
        const int px = p - py * Ww;
        const float dyv = (cy - (float)(py * 8 + 4)) * inv_soi;
        const float dxb = (cx - (float)(px * 8 + 4)) * inv_soi;
        const ull dy2 = pk2(dyv, dyv);
        ull dxp[4];
        #pragma unroll
        for (int k = 0; k < 4; k++)
            dxp[k] = pk2(dxb + (float)(2 * k) * step, dxb + (float)(2 * k + 1) * step);

        ull f[4][8];
        #pragma unroll
        for (int c = 0; c < 8; c++) {
            float4 v0 = *(const float4*)&fb[c * HW + p];
            float4 v1 = *(const float4*)&fb[c * HW + p + 4];
            f[0][c] = pk2(v0.x, v0.y);
            f[1][c] = pk2(v0.z, v0.w);
            f[2][c] = pk2(v1.x, v1.y);
            f[3][c] = pk2(v1.z, v1.w);
        }

        // layer 0: 10 -> 8, relu
        ull h0[4][8];
        #pragma unroll
        for (int j = 0; j < 8; j++) {
            const ulonglong2* r = (const ulonglong2*)sw0[j];
            ulonglong2 wA = r[0], wB = r[1], wC = r[2], wD = r[3], wE = r[4];
            ull bias = sw0[j][10];
            ull a[4];
            #pragma unroll
            for (int k = 0; k < 4; k++) {
                a[k] = fma2(wA.y, dy2, bias);
                a[k] = fma2(wA.x, dxp[k], a[k]);
                a[k] = fma2(wB.x, f[k][0], a[k]);
                a[k] = fma2(wB.y, f[k][1], a[k]);
                a[k] = fma2(wC.x, f[k][2], a[k]);
                a[k] = fma2(wC.y, f[k][3], a[k]);
                a[k] = fma2(wD.x, f[k][4], a[k]);
                a[k] = fma2(wD.y, f[k][5], a[k]);
                a[k] = fma2(wE.x, f[k][6], a[k]);
                a[k] = fma2(wE.y, f[k][7], a[k]);
                h0[k][j] = relu2(a[k]);
            }
        }

        // layer 1: 8 -> 8, relu
        ull h1[4][8];
        #pragma unroll
        for (int j = 0; j < 8; j++) {
            const ulonglong2* r = (const ulonglong2*)sw1[j];
            ulonglong2 wA = r[0], wB = r[1], wC = r[2], wD = r[3];
            ull bias = sw1[j][8];
            #pragma unroll
            for (int k = 0; k < 4; k++) {
                ull a = fma2(wA.x, h0[k][0], bias);
                a = fma2(wA.y, h0[k][1], a);
                a = fma2(wB.x, h0[k][2], a);
                a = fma2(wB.y, h0[k][3], a);
                a = fma2(wC.x, h0[k][4], a);
                a = fma2(wC.y, h0[k][5], a);
                a = fma2(wD.x, h0[k][6], a);
                a = fma2(wD.y, h0[k][7], a);
                h1[k][j] = relu2(a);
            }
        }

        // layer 2: 8 -> 1
        {
            const ulonglong2* r = (const ulonglong2*)sw2;
            ulonglong2 wA = r[0], wB = r[1], wC = r[2], wD = r[3];
            ull bias = sw2[8];
            float o[8];
            #pragma unroll
            for (int k = 0; k < 4; k++) {
                ull a = fma2(wA.x, h1[k][0], bias);
                a = fma2(wA.y, h1[k][1], a);
                a = fma2(wB.x, h1[k][2], a);
                a = fma2(wB.y, h1[k][3], a);
                a = fma2(wC.x, h1[k][4], a);
                a = fma2(wC.y, h1[k][5], a);
                a = fma2(wD.x, h1[k][6], a);
                a = fma2(wD.y, h1[k][7], a);
                upk2(a, o[2 * k], o[2 * k + 1]);
            }
            *(float4*)&Lg[p]     = make_float4(o[0], o[1], o[2], o[3]);
            *(float4*)&Lg[p + 4] = make_float4(o[4], o[5], o[6], o[7]);
        }
    }
}

// ---------------------------------------------------------------------------
// Kernel B: 2x aligned-bilinear + sigmoid + dice partials.
// One block per instance; logit tile staged in SMEM; 512 threads.
// ---------------------------------------------------------------------------
__global__ __launch_bounds__(512) void dice_kernel(const float* __restrict__ gt)
{
    extern __shared__ float sL[];   // HW floats = 54.4 KB
    const int inst = blockIdx.x;
    const float* __restrict__ L = g_logits + (size_t)inst * HW;
    const float* __restrict__ T = gt + (size_t)inst * OHW;

    for (int i = threadIdx.x; i < HW; i += 512) sL[i] = L[i];
    __syncthreads();

    float si = 0.0f, sx = 0.0f, st = 0.0f;

    const int NQ = OHW / 4;
    for (int q = threadIdx.x; q < NQ; q += 512) {
        const int oy = q / (OW / 4);
        const int ox = (q - oy * (OW / 4)) * 4;
        const int j  = (oy > 0) ? (oy - 1) : 0;
        const int y0 = j >> 1;
        const int y1 = min(y0 + 1, Hh - 1);
        const float* r0 = sL + y0 * Ww;
        const float* r1 = sL + y1 * Ww;
        const bool vodd = (j & 1) != 0;

        const int i0 = (ox > 0) ? (ox - 1) : 0;
        float v[4];
        int ii[4] = { i0, ox, ox + 1, ox + 2 };
        if (!vodd) {
            #pragma unroll
            for (int k = 0; k < 4; k++) {
                int x0 = ii[k] >> 1;
                int x1 = min(x0 + 1, Ww - 1);
                float a = r0[x0];
                v[k] = (ii[k] & 1) ? 0.5f * (a + r0[x1]) : a;
            }
        } else {
            #pragma unroll
            for (int k = 0; k < 4; k++) {
                int x0 = ii[k] >> 1;
                int x1 = min(x0 + 1, Ww - 1);
                float a = r0[x0], b = r1[x0];
                v[k] = (ii[k] & 1) ? 0.25f * ((a + r0[x1]) + (b + r1[x1]))
                                   : 0.5f  * (a + b);
            }
        }

        const float4 t4 = __ldcs((const float4*)&T[oy * OW + ox]);
        const float tv[4] = { t4.x, t4.y, t4.z, t4.w };
        #pragma unroll
        for (int k = 0; k < 4; k++) {
            float s = __fdividef(1.0f, 1.0f + __expf(-v[k]));
            si = fmaf(s, tv[k], si);
            sx = fmaf(s, s, sx);
            st = fmaf(tv[k], tv[k], st);
        }
    }

    __shared__ float sm[3][16];
    int lane = threadIdx.x & 31;
    int wid  = threadIdx.x >> 5;
    #pragma unroll
    for (int o = 16; o; o >>= 1) {
        si += __shfl_down_sync(0xffffffffu, si, o);
        sx += __shfl_down_sync(0xffffffffu, sx, o);
        st += __shfl_down_sync(0xffffffffu, st, o);
    }
    if (lane == 0) { sm[0][wid] = si; sm[1][wid] = sx; sm[2][wid] = st; }
    __syncthreads();
    if (wid == 0) {
        si = (lane < 16) ? sm[0][lane] : 0.0f;
        sx = (lane < 16) ? sm[1][lane] : 0.0f;
        st = (lane < 16) ? sm[2][lane] : 0.0f;
        #pragma unroll
        for (int o = 8; o; o >>= 1) {
            si += __shfl_down_sync(0xffffffffu, si, o);
            sx += __shfl_down_sync(0xffffffffu, sx, o);
            st += __shfl_down_sync(0xffffffffu, st, o);
        }
        if (lane == 0) {
            g_inter[inst] = si;
            g_ux[inst]    = sx;
            g_ut[inst]    = st;
        }
    }
}

__global__ __launch_bounds__(512) void loss_kernel(float* __restrict__ out, int n)
{
    __shared__ float sm[16];
    float acc = 0.0f;
    for (int i = threadIdx.x; i < n; i += 512) {
        float u = g_ux[i] + g_ut[i] + 1e-5f;
        acc += 1.0f - 2.0f * g_inter[i] / u;
    }
    int lane = threadIdx.x & 31;
    int wid  = threadIdx.x >> 5;
    #pragma unroll
    for (int o = 16; o; o >>= 1) acc += __shfl_down_sync(0xffffffffu, acc, o);
    if (lane == 0) sm[wid] = acc;
    __syncthreads();
    if (wid == 0) {
        acc = (lane < 16) ? sm[lane] : 0.0f;
        #pragma unroll
        for (int o = 8; o; o >>= 1) acc += __shfl_down_sync(0xffffffffu, acc, o);
        if (lane == 0) out[0] = acc / (float)n;
    }
}

extern "C" void kernel_launch(void* const* d_in, const int* in_sizes, int n_in,
                              void* d_out, int out_size)
{
    const float* feats   = (const float*)d_in[0];
    const float* params  = (const float*)d_in[1];
    const float* locs    = (const float*)d_in[2];
    const float* gt      = (const float*)d_in[3];
    const int*   im_inds = (const int*)d_in[4];
    const int*   fpn     = (const int*)d_in[5];

    int n = in_sizes[1] / NP;
    if (n > MAXI) n = MAXI;

    cudaFuncSetAttribute(dice_kernel, cudaFuncAttributeMaxDynamicSharedMemorySize,
                         HW * (int)sizeof(float));

    logits_kernel<<<2 * n, 256>>>(feats, params, locs, im_inds, fpn);
    dice_kernel<<<n, 512, HW * sizeof(float)>>>(gt);
    loss_kernel<<<1, 512>>>((float*)d_out, n);
}

// round 5
// speedup vs baseline: 1.1127x; 1.1127x over previous
#include <cuda_runtime.h>

#define Hh 100
#define Ww 136
#define HW (Hh * Ww)        // 13600
#define OH (2 * Hh)         // 200
#define OW (2 * Ww)         // 272
#define OHW (OH * OW)       // 54400
#define NP 169
#define MAXI 512
#define BLKS_PER_INST 4

typedef unsigned long long ull;

__device__ float g_logits[MAXI * HW];
__device__ float g_inter[MAXI];
__device__ float g_ux[MAXI];
__device__ float g_ut[MAXI];

// ---- packed f32x2 helpers (sm_100+) ----
__device__ __forceinline__ ull pk2(float lo, float hi) {
    ull r; asm("mov.b64 %0, {%1,%2};" : "=l"(r) : "f"(lo), "f"(hi)); return r;
}
__device__ __forceinline__ ull fma2(ull a, ull b, ull c) {
    ull d; asm("fma.rn.f32x2 %0, %1, %2, %3;" : "=l"(d) : "l"(a), "l"(b), "l"(c)); return d;
}
__device__ __forceinline__ ull relu2(ull a) {
    float x, y;
    asm("mov.b64 {%0,%1}, %2;" : "=f"(x), "=f"(y) : "l"(a));
    x = fmaxf(x, 0.0f); y = fmaxf(y, 0.0f);
    ull r; asm("mov.b64 %0, {%1,%2};" : "=l"(r) : "f"(x), "f"(y)); return r;
}
__device__ __forceinline__ void upk2(ull a, float& x, float& y) {
    asm("mov.b64 {%0,%1}, %2;" : "=f"(x), "=f"(y) : "l"(a));
}

// ---------------------------------------------------------------------------
// Kernel A: dynamic mask head -> logits.
// Accumulator-centric ordering with TRANSPOSED weights (st[c][j]) so the live
// set is {acc[2][8], prev[2][8], one 8-wide weight column} -> fits 128 regs
// -> 2 blocks/SM (16 warps). Channel loops are unroll-1 to stop ptxas from
// hoisting all weight loads (the R2 spill cause). 4 blocks per instance.
// ---------------------------------------------------------------------------
__global__ __launch_bounds__(256, 2) void logits_kernel(
    const float* __restrict__ feats,
    const float* __restrict__ params,
    const float* __restrict__ locs,
    const int*   __restrict__ im_inds,
    const int*   __restrict__ fpn)
{
    const int inst = blockIdx.x / BLKS_PER_INST;
    const int part = blockIdx.x % BLKS_PER_INST;
    const int tid  = threadIdx.x;

    // transposed, duplicated (lo=hi) weights
    __shared__ __align__(16) ull st0[10][8];  // layer0: st0[c][j], c: 0=x,1=y,2..9=feat
    __shared__ __align__(16) ull st1[8][8];   // layer1: st1[c][j]
    __shared__ __align__(16) ull st2[8];      // layer2 weights
    __shared__ __align__(16) ull sb0[8];      // biases
    __shared__ __align__(16) ull sb1[8];
    __shared__ ull sb2;

    for (int i = tid; i < NP; i += 256) {
        float w = params[inst * NP + i];
        ull d = pk2(w, w);
        if      (i < 80)  st0[i % 10][i / 10] = d;
        else if (i < 144) { int k = i - 80; st1[k & 7][k >> 3] = d; }
        else if (i < 152) st2[i - 144] = d;
        else if (i < 160) sb0[i - 152] = d;
        else if (i < 168) sb1[i - 160] = d;
        else              sb2 = d;
    }
    __syncthreads();

    const float cx = locs[inst * 2 + 0];
    const float cy = locs[inst * 2 + 1];
    const float inv_soi = 1.0f / (float)(8 << fpn[inst]);
    const float step = -8.0f * inv_soi;
    const float* __restrict__ fb = feats + (size_t)im_inds[inst] * 8 * HW;
    float* __restrict__ Lg = g_logits + (size_t)inst * HW;

    // 4-px units: HW/4 = 3400 (Ww%4==0 so units never cross rows)
    const int NU   = HW / 4;                    // 3400
    const int per  = NU / BLKS_PER_INST;        // 850
    const int ubeg = part * per;
    const int uend = ubeg + per;

    for (int u = ubeg + tid; u < uend; u += 256) {
        const int p  = u * 4;
        const int py = p / Ww;
        const int px = p - py * Ww;
        const float dyv = (cy - (float)(py * 8 + 4)) * inv_soi;
        const float dxb = (cx - (float)(px * 8 + 4)) * inv_soi;
        const ull dy2 = pk2(dyv, dyv);
        const ull dx0 = pk2(dxb, dxb + step);
        const ull dx1 = pk2(dxb + 2.0f * step, dxb + 3.0f * step);

        ull f[2][8];
        #pragma unroll
        for (int c = 0; c < 8; c++) {
            float4 v = *(const float4*)&fb[c * HW + p];
            f[0][c] = pk2(v.x, v.y);
            f[1][c] = pk2(v.z, v.w);
        }

        // ---- layer 0 (accumulator-centric): init bias + x,y terms ----
        ull a0[2][8], a1[2][8];     // a0 = current accumulators, a1 reused later
        {
            const ulonglong2* bb = (const ulonglong2*)sb0;
            const ulonglong2* wx = (const ulonglong2*)st0[0];
            const ulonglong2* wy = (const ulonglong2*)st0[1];
            #pragma unroll
            for (int h = 0; h < 4; h++) {
                ulonglong2 b = bb[h], vx = wx[h], vy = wy[h];
                int j = 2 * h;
                ull t0 = fma2(vx.x, dx0, fma2(vy.x, dy2, b.x));
                ull t1 = fma2(vx.y, dx0, fma2(vy.y, dy2, b.y));
                ull t2 = fma2(vx.x, dx1, fma2(vy.x, dy2, b.x));
                ull t3 = fma2(vx.y, dx1, fma2(vy.y, dy2, b.y));
                a0[0][j] = t0; a0[0][j + 1] = t1;
                a0[1][j] = t2; a0[1][j + 1] = t3;
            }
        }
        // feature channels: outer-product updates, unroll-1 to bound pressure
        #pragma unroll 1
        for (int c = 0; c < 8; c++) {
            const ulonglong2* wc = (const ulonglong2*)st0[c + 2];
            ull fc0 = f[0][c], fc1 = f[1][c];
            #pragma unroll
            for (int h = 0; h < 4; h++) {
                ulonglong2 w = wc[h];
                int j = 2 * h;
                a0[0][j]     = fma2(w.x, fc0, a0[0][j]);
                a0[0][j + 1] = fma2(w.y, fc0, a0[0][j + 1]);
                a0[1][j]     = fma2(w.x, fc1, a0[1][j]);
                a0[1][j + 1] = fma2(w.y, fc1, a0[1][j + 1]);
            }
        }
        #pragma unroll
        for (int k = 0; k < 2; k++)
            #pragma unroll
            for (int j = 0; j < 8; j++) a0[k][j] = relu2(a0[k][j]);   // h0 in a0

        // ---- layer 1 ----
        {
            const ulonglong2* bb = (const ulonglong2*)sb1;
            #pragma unroll
            for (int h = 0; h < 4; h++) {
                ulonglong2 b = bb[h];
                int j = 2 * h;
                a1[0][j] = b.x; a1[0][j + 1] = b.y;
                a1[1][j] = b.x; a1[1][j + 1] = b.y;
            }
        }
        #pragma unroll 1
        for (int c = 0; c < 8; c++) {
            const ulonglong2* wc = (const ulonglong2*)st1[c];
            ull hc0 = a0[0][c], hc1 = a0[1][c];
            #pragma unroll
            for (int h = 0; h < 4; h++) {
                ulonglong2 w = wc[h];
                int j = 2 * h;
                a1[0][j]     = fma2(w.x, hc0, a1[0][j]);
                a1[0][j + 1] = fma2(w.y, hc0, a1[0][j + 1]);
                a1[1][j]     = fma2(w.x, hc1, a1[1][j]);
                a1[1][j + 1] = fma2(w.y, hc1, a1[1][j + 1]);
            }
        }

        // ---- layer 2 (h1 = relu(a1) folded in) ----
        {
            const ulonglong2* wc = (const ulonglong2*)st2;
            ull o0 = sb2, o1 = sb2;
            #pragma unroll
            for (int h = 0; h < 4; h++) {
                ulonglong2 w = wc[h];
                int j = 2 * h;
                o0 = fma2(w.x, relu2(a1[0][j]), o0);
                o0 = fma2(w.y, relu2(a1[0][j + 1]), o0);
                o1 = fma2(w.x, relu2(a1[1][j]), o1);
                o1 = fma2(w.y, relu2(a1[1][j + 1]), o1);
            }
            float4 o;
            upk2(o0, o.x, o.y);
            upk2(o1, o.z, o.w);
            *(float4*)&Lg[p] = o;
        }
    }
}

// ---------------------------------------------------------------------------
// Kernel B: 2x aligned-bilinear + sigmoid + dice partials.
// ---------------------------------------------------------------------------
__global__ __launch_bounds__(512) void dice_kernel(const float* __restrict__ gt)
{
    extern __shared__ float sL[];   // HW floats = 54.4 KB
    const int inst = blockIdx.x;
    const float* __restrict__ L = g_logits + (size_t)inst * HW;
    const float* __restrict__ T = gt + (size_t)inst * OHW;

    for (int i = threadIdx.x; i < HW; i += 512) sL[i] = L[i];
    __syncthreads();

    float si = 0.0f, sx = 0.0f, st = 0.0f;

    const int NQ = OHW / 4;
    for (int q = threadIdx.x; q < NQ; q += 512) {
        const int oy = q / (OW / 4);
        const int ox = (q - oy * (OW / 4)) * 4;
        const int j  = (oy > 0) ? (oy - 1) : 0;
        const int y0 = j >> 1;
        const int y1 = min(y0 + 1, Hh - 1);
        const float* r0 = sL + y0 * Ww;
        const float* r1 = sL + y1 * Ww;
        const bool vodd = (j & 1) != 0;

        const int i0 = (ox > 0) ? (ox - 1) : 0;
        float v[4];
        int ii[4] = { i0, ox, ox + 1, ox + 2 };
        if (!vodd) {
            #pragma unroll
            for (int k = 0; k < 4; k++) {
                int x0 = ii[k] >> 1;
                int x1 = min(x0 + 1, Ww - 1);
                float a = r0[x0];
                v[k] = (ii[k] & 1) ? 0.5f * (a + r0[x1]) : a;
            }
        } else {
            #pragma unroll
            for (int k = 0; k < 4; k++) {
                int x0 = ii[k] >> 1;
                int x1 = min(x0 + 1, Ww - 1);
                float a = r0[x0], b = r1[x0];
                v[k] = (ii[k] & 1) ? 0.25f * ((a + r0[x1]) + (b + r1[x1]))
                                   : 0.5f  * (a + b);
            }
        }

        const float4 t4 = __ldcs((const float4*)&T[oy * OW + ox]);
        const float tv[4] = { t4.x, t4.y, t4.z, t4.w };
        #pragma unroll
        for (int k = 0; k < 4; k++) {
            float s = __fdividef(1.0f, 1.0f + __expf(-v[k]));
            si = fmaf(s, tv[k], si);
            sx = fmaf(s, s, sx);
            st = fmaf(tv[k], tv[k], st);
        }
    }

    __shared__ float sm[3][16];
    int lane = threadIdx.x & 31;
    int wid  = threadIdx.x >> 5;
    #pragma unroll
    for (int o = 16; o; o >>= 1) {
        si += __shfl_down_sync(0xffffffffu, si, o);
        sx += __shfl_down_sync(0xffffffffu, sx, o);
        st += __shfl_down_sync(0xffffffffu, st, o);
    }
    if (lane == 0) { sm[0][wid] = si; sm[1][wid] = sx; sm[2][wid] = st; }
    __syncthreads();
    if (wid == 0) {
        si = (lane < 16) ? sm[0][lane] : 0.0f;
        sx = (lane < 16) ? sm[1][lane] : 0.0f;
        st = (lane < 16) ? sm[2][lane] : 0.0f;
        #pragma unroll
        for (int o = 8; o; o >>= 1) {
            si += __shfl_down_sync(0xffffffffu, si, o);
            sx += __shfl_down_sync(0xffffffffu, sx, o);
            st += __shfl_down_sync(0xffffffffu, st, o);
        }
        if (lane == 0) {
            g_inter[inst] = si;
            g_ux[inst]    = sx;
            g_ut[inst]    = st;
        }
    }
}

__global__ __launch_bounds__(512) void loss_kernel(float* __restrict__ out, int n)
{
    __shared__ float sm[16];
    float acc = 0.0f;
    for (int i = threadIdx.x; i < n; i += 512) {
        float u = g_ux[i] + g_ut[i] + 1e-5f;
        acc += 1.0f - 2.0f * g_inter[i] / u;
    }
    int lane = threadIdx.x & 31;
    int wid  = threadIdx.x >> 5;
    #pragma unroll
    for (int o = 16; o; o >>= 1) acc += __shfl_down_sync(0xffffffffu, acc, o);
    if (lane == 0) sm[wid] = acc;
    __syncthreads();
    if (wid == 0) {
        acc = (lane < 16) ? sm[lane] : 0.0f;
        #pragma unroll
        for (int o = 8; o; o >>= 1) acc += __shfl_down_sync(0xffffffffu, acc, o);
        if (lane == 0) out[0] = acc / (float)n;
    }
}

extern "C" void kernel_launch(void* const* d_in, const int* in_sizes, int n_in,
                              void* d_out, int out_size)
{
    const float* feats   = (const float*)d_in[0];
    const float* params  = (const float*)d_in[1];
    const float* locs    = (const float*)d_in[2];
    const float* gt      = (const float*)d_in[3];
    const int*   im_inds = (const int*)d_in[4];
    const int*   fpn     = (const int*)d_in[5];

    int n = in_sizes[1] / NP;
    if (n > MAXI) n = MAXI;

    cudaFuncSetAttribute(dice_kernel, cudaFuncAttributeMaxDynamicSharedMemorySize,
                         HW * (int)sizeof(float));

    logits_kernel<<<BLKS_PER_INST * n, 256>>>(feats, params, locs, im_inds, fpn);
    dice_kernel<<<n, 512, HW * sizeof(float)>>>(gt);
    loss_kernel<<<1, 512>>>((float*)d_out, n);
}